// round 1
// baseline (speedup 1.0000x reference)
#include <cuda_runtime.h>
#include <cuda_bf16.h>

// ---------------- problem constants ----------------
#define NA 500000
// degree offsets: [0,20000,100000,250000,400000,475000,495000,500000]
static const int H_DEG_CNT[7] = {20000, 80000, 150000, 150000, 75000, 20000, 5000};
static const int H_DEG_OFF[8] = {0, 20000, 100000, 250000, 400000, 475000, 495000, 500000};

// ---------------- scratch (device globals; no allocation allowed) ----------------
__device__ float    g_h1[(size_t)NA * 64];
__device__ float    g_h2[(size_t)NA * 64];
__device__ float    g_h3[(size_t)NA * 128];
__device__ float    g_gsum[1024 * 128];
__device__ unsigned g_gmax[1024 * 128];

// ---------------- helpers ----------------
__device__ __forceinline__ unsigned enc_f(float f) {
    unsigned u = __float_as_uint(f);
    return (u >> 31) ? ~u : (u | 0x80000000u);
}
__device__ __forceinline__ float dec_f(unsigned u) {
    return (u >> 31) ? __uint_as_float(u & 0x7FFFFFFFu) : __uint_as_float(~u);
}

// ---------------- graph conv (+tanh, +bn1) ----------------
// One block = 32 atoms of a single degree segment.
// Stage: self row (F floats) and neighbor-sum row (F floats) into SMEM.
// Compute: each thread produces 2 output features x 4 atoms (8 accs).
template <int F>
__global__ void gc_kernel(const float* __restrict__ feat,
                          const int* __restrict__ adj, int d,
                          const float* __restrict__ Ws,   // offset to degree d: [F][64]
                          const float* __restrict__ Wn,   // offset to d-1 (null for d=0)
                          const float* __restrict__ bias, // offset to degree d: [64]
                          const float* __restrict__ bn_g, const float* __restrict__ bn_b,
                          const float* __restrict__ bn_m, const float* __restrict__ bn_v,
                          float* __restrict__ out,
                          int atom0, int cnt)
{
    __shared__ float s_self[32][F];
    __shared__ float s_sum[32][F];
    __shared__ int   s_adj[32][6];

    const int t = threadIdx.x;
    const int ablk = blockIdx.x * 32;
    const int nat = min(32, cnt - ablk);

    if (d > 0) {
        for (int idx = t; idx < nat * d; idx += 256) {
            int a = idx / d, m = idx - a * d;
            s_adj[a][m] = adj[(ablk + a) * d + m];
        }
    }
    __syncthreads();

    for (int idx = t; idx < nat * F; idx += 256) {
        int a = idx / F, k = idx - a * F;
        int gi = atom0 + ablk + a;
        s_self[a][k] = feat[gi * F + k];
        if (d > 0) {
            float s = 0.f;
            #pragma unroll 6
            for (int m = 0; m < d; m++)
                s += feat[s_adj[a][m] * F + k];
            s_sum[a][k] = s;
        }
    }
    __syncthreads();

    const int j   = (t & 31) * 2;   // output feature pair (warp-uniform atoms)
    const int grp = t >> 5;         // 8 groups x 4 atoms

    float acc[4][2];
    #pragma unroll
    for (int r = 0; r < 4; r++) { acc[r][0] = bias[j]; acc[r][1] = bias[j + 1]; }

    for (int k = 0; k < F; k++) {
        float2 w = *(const float2*)(Ws + k * 64 + j);
        #pragma unroll
        for (int r = 0; r < 4; r++) {
            float x = s_self[grp * 4 + r][k];
            acc[r][0] = fmaf(x, w.x, acc[r][0]);
            acc[r][1] = fmaf(x, w.y, acc[r][1]);
        }
    }
    if (d > 0) {
        for (int k = 0; k < F; k++) {
            float2 w = *(const float2*)(Wn + k * 64 + j);
            #pragma unroll
            for (int r = 0; r < 4; r++) {
                float x = s_sum[grp * 4 + r][k];
                acc[r][0] = fmaf(x, w.x, acc[r][0]);
                acc[r][1] = fmaf(x, w.y, acc[r][1]);
            }
        }
    }

    // bn applied to tanh(conv)
    float sc0 = bn_g[j]     * rsqrtf(bn_v[j]     + 1e-3f);
    float sc1 = bn_g[j + 1] * rsqrtf(bn_v[j + 1] + 1e-3f);
    float sh0 = bn_b[j]     - bn_m[j]     * sc0;
    float sh1 = bn_b[j + 1] - bn_m[j + 1] * sc1;

    #pragma unroll
    for (int r = 0; r < 4; r++) {
        int a = grp * 4 + r;
        if (a < nat) {
            int gi = atom0 + ablk + a;
            out[gi * 64 + j]     = sc0 * tanhf(acc[r][0]) + sh0;
            out[gi * 64 + j + 1] = sc1 * tanhf(acc[r][1]) + sh1;
        }
    }
}

// ---------------- graph pool (elementwise max over self + neighbors) ----------------
__global__ void pool_kernel(const float* __restrict__ in, float* __restrict__ out,
                            const int* __restrict__ a1, const int* __restrict__ a2,
                            const int* __restrict__ a3, const int* __restrict__ a4,
                            const int* __restrict__ a5, const int* __restrict__ a6)
{
    int idx  = blockIdx.x * 256 + threadIdx.x;  // grid sized exactly NA*64/256
    int atom = idx >> 6;
    int j    = idx & 63;
    float v  = in[idx];

    if (atom >= 20000) {
        const int* ap; int d, li;
        if      (atom < 100000) { d = 1; ap = a1; li = atom - 20000;  }
        else if (atom < 250000) { d = 2; ap = a2; li = atom - 100000; }
        else if (atom < 400000) { d = 3; ap = a3; li = atom - 250000; }
        else if (atom < 475000) { d = 4; ap = a4; li = atom - 400000; }
        else if (atom < 495000) { d = 5; ap = a5; li = atom - 475000; }
        else                    { d = 6; ap = a6; li = atom - 495000; }
        for (int m = 0; m < d; m++) {
            int nb = ap[li * d + m];
            v = fmaxf(v, in[nb * 64 + j]);
        }
    }
    out[idx] = v;
}

// ---------------- dense1: [64]->[128], tanh, bn3 ----------------
__global__ void dense1_kernel(const float* __restrict__ in,
                              const float* __restrict__ W,   // [64][128]
                              const float* __restrict__ b,   // [128]
                              const float* __restrict__ bn_g, const float* __restrict__ bn_b,
                              const float* __restrict__ bn_m, const float* __restrict__ bn_v,
                              float* __restrict__ out)
{
    __shared__ float s_in[16][64];
    const int t = threadIdx.x;
    const int ablk = blockIdx.x * 16;

    for (int idx = t; idx < 16 * 64; idx += 256) {
        int a = idx >> 6, k = idx & 63;
        s_in[a][k] = in[(ablk + a) * 64 + k];
    }
    __syncthreads();

    const int j   = (t & 63) * 2;   // 128 outputs
    const int grp = t >> 6;         // 4 groups x 4 atoms

    float acc[4][2];
    #pragma unroll
    for (int r = 0; r < 4; r++) { acc[r][0] = b[j]; acc[r][1] = b[j + 1]; }

    for (int k = 0; k < 64; k++) {
        float2 w = *(const float2*)(W + k * 128 + j);
        #pragma unroll
        for (int r = 0; r < 4; r++) {
            float x = s_in[grp * 4 + r][k];
            acc[r][0] = fmaf(x, w.x, acc[r][0]);
            acc[r][1] = fmaf(x, w.y, acc[r][1]);
        }
    }

    float sc0 = bn_g[j]     * rsqrtf(bn_v[j]     + 1e-3f);
    float sc1 = bn_g[j + 1] * rsqrtf(bn_v[j + 1] + 1e-3f);
    float sh0 = bn_b[j]     - bn_m[j]     * sc0;
    float sh1 = bn_b[j + 1] - bn_m[j + 1] * sc1;

    #pragma unroll
    for (int r = 0; r < 4; r++) {
        int a = grp * 4 + r;
        out[(size_t)(ablk + a) * 128 + j]     = sc0 * tanhf(acc[r][0]) + sh0;
        out[(size_t)(ablk + a) * 128 + j + 1] = sc1 * tanhf(acc[r][1]) + sh1;
    }
}

// ---------------- segment gather: init + atomic sum/max ----------------
__global__ void init_gather_kernel(float* __restrict__ gsum, unsigned* __restrict__ gmax)
{
    int idx = blockIdx.x * 256 + threadIdx.x;
    if (idx < 1024 * 128) { gsum[idx] = 0.f; gmax[idx] = 0u; }
}

__global__ void gather_kernel(const float* __restrict__ h,
                              const int* __restrict__ membership,
                              float* __restrict__ gsum, unsigned* __restrict__ gmax)
{
    int idx  = blockIdx.x * 256 + threadIdx.x;  // exactly NA*128 threads
    int atom = idx >> 7;
    int j    = idx & 127;
    int m    = membership[atom];
    float v  = h[idx];
    atomicAdd(&gsum[m * 128 + j], v);
    atomicMax(&gmax[m * 128 + j], enc_f(v));
}

// ---------------- head: tanh(concat) -> sigmoid(dense 256->64) -> dense 64->1 ----------------
__global__ void head_kernel(const float* __restrict__ gsum, const unsigned* __restrict__ gmax,
                            const float* __restrict__ d2W, const float* __restrict__ d2b,
                            const float* __restrict__ d3W, const float* __restrict__ d3b,
                            float* __restrict__ out)
{
    __shared__ float sg[256];
    __shared__ float sred[64];
    const int row = blockIdx.x;
    const int t   = threadIdx.x;  // 64 threads

    for (int k = t; k < 256; k += 64) {
        float v = (k < 128) ? gsum[row * 128 + k] : dec_f(gmax[row * 128 + (k - 128)]);
        sg[k] = tanhf(v);
    }
    __syncthreads();

    float acc = d2b[t];
    for (int k = 0; k < 256; k++)
        acc = fmaf(sg[k], d2W[k * 64 + t], acc);
    float s = 1.f / (1.f + expf(-acc));

    sred[t] = s * d3W[t];
    __syncthreads();
    if (t < 32) {
        float x = sred[t] + sred[t + 32];
        #pragma unroll
        for (int off = 16; off; off >>= 1)
            x += __shfl_down_sync(0xffffffffu, x, off);
        if (t == 0) out[row] = x + d3b[0];
    }
}

// ---------------- launch ----------------
extern "C" void kernel_launch(void* const* d_in, const int* in_sizes, int n_in,
                              void* d_out, int out_size)
{
    const float* feat       = (const float*)d_in[0];
    const int*   membership = (const int*)d_in[1];
    const int*   adj[6]     = {(const int*)d_in[2], (const int*)d_in[3], (const int*)d_in[4],
                               (const int*)d_in[5], (const int*)d_in[6], (const int*)d_in[7]};
    const float* gc1_Wn = (const float*)d_in[8];
    const float* gc1_Ws = (const float*)d_in[9];
    const float* gc1_b  = (const float*)d_in[10];
    const float* gc2_Wn = (const float*)d_in[11];
    const float* gc2_Ws = (const float*)d_in[12];
    const float* gc2_b  = (const float*)d_in[13];
    const float* bn1g = (const float*)d_in[14];
    const float* bn1b = (const float*)d_in[15];
    const float* bn1m = (const float*)d_in[16];
    const float* bn1v = (const float*)d_in[17];
    const float* bn3g = (const float*)d_in[18];
    const float* bn3b = (const float*)d_in[19];
    const float* bn3m = (const float*)d_in[20];
    const float* bn3v = (const float*)d_in[21];
    const float* d1W = (const float*)d_in[22];
    const float* d1b = (const float*)d_in[23];
    const float* d2W = (const float*)d_in[24];
    const float* d2b = (const float*)d_in[25];
    const float* d3W = (const float*)d_in[26];
    const float* d3b = (const float*)d_in[27];

    float *h1, *h2, *h3, *gsum; unsigned* gmax;
    cudaGetSymbolAddress((void**)&h1, g_h1);
    cudaGetSymbolAddress((void**)&h2, g_h2);
    cudaGetSymbolAddress((void**)&h3, g_h3);
    cudaGetSymbolAddress((void**)&gsum, g_gsum);
    cudaGetSymbolAddress((void**)&gmax, g_gmax);

    // ---- gc1 (+tanh +bn1): feat[NA,75] -> h1[NA,64]
    for (int d = 0; d <= 6; d++) {
        int cnt = H_DEG_CNT[d];
        dim3 grid((cnt + 31) / 32);
        gc_kernel<75><<<grid, 256>>>(
            feat, d ? adj[d - 1] : nullptr, d,
            gc1_Ws + d * 75 * 64, d ? gc1_Wn + (d - 1) * 75 * 64 : nullptr, gc1_b + d * 64,
            bn1g, bn1b, bn1m, bn1v, h1, H_DEG_OFF[d], cnt);
    }

    // ---- pool1: h1 -> h2
    pool_kernel<<<NA * 64 / 256, 256>>>(h1, h2, adj[0], adj[1], adj[2], adj[3], adj[4], adj[5]);

    // ---- gc2 (+tanh +bn1): h2[NA,64] -> h1[NA,64]
    for (int d = 0; d <= 6; d++) {
        int cnt = H_DEG_CNT[d];
        dim3 grid((cnt + 31) / 32);
        gc_kernel<64><<<grid, 256>>>(
            h2, d ? adj[d - 1] : nullptr, d,
            gc2_Ws + d * 64 * 64, d ? gc2_Wn + (d - 1) * 64 * 64 : nullptr, gc2_b + d * 64,
            bn1g, bn1b, bn1m, bn1v, h1, H_DEG_OFF[d], cnt);
    }

    // ---- pool2: h1 -> h2
    pool_kernel<<<NA * 64 / 256, 256>>>(h1, h2, adj[0], adj[1], adj[2], adj[3], adj[4], adj[5]);

    // ---- dense1 + tanh + bn3: h2[NA,64] -> h3[NA,128]
    dense1_kernel<<<NA / 16, 256>>>(h2, d1W, d1b, bn3g, bn3b, bn3m, bn3v, h3);

    // ---- segment gather (sum + max) over membership
    init_gather_kernel<<<(1024 * 128 + 255) / 256, 256>>>(gsum, gmax);
    gather_kernel<<<NA * 128 / 256, 256>>>(h3, membership, gsum, gmax);

    // ---- head: tanh -> dense(256,64)+sigmoid -> dense(64,1)
    head_kernel<<<1024, 64>>>(gsum, gmax, d2W, d2b, d3W, d3b, (float*)d_out);
}

// round 2
// speedup vs baseline: 1.3748x; 1.3748x over previous
#include <cuda_runtime.h>
#include <cuda_bf16.h>

// ---------------- problem constants ----------------
#define NA 500000
static const int H_DEG_CNT[7] = {20000, 80000, 150000, 150000, 75000, 20000, 5000};
static const int H_DEG_OFF[8] = {0, 20000, 100000, 250000, 400000, 475000, 495000, 500000};

// ---------------- scratch (device globals; no allocation allowed) ----------------
__device__ float    g_h1[(size_t)NA * 64];
__device__ float    g_h2[(size_t)NA * 64];
__device__ float    g_gsum[1024 * 128];
__device__ unsigned g_gmax[1024 * 128];

// ---------------- helpers ----------------
__device__ __forceinline__ unsigned enc_f(float f) {
    unsigned u = __float_as_uint(f);
    return (u >> 31) ? ~u : (u | 0x80000000u);
}
__device__ __forceinline__ float dec_f(unsigned u) {
    return (u >> 31) ? __uint_as_float(u & 0x7FFFFFFFu) : __uint_as_float(~u);
}
__device__ __forceinline__ float tanh_fast(float x) {
    float y;
    asm("tanh.approx.f32 %0, %1;" : "=f"(y) : "f"(x));
    return y;
}
#define COMP(v, i) ((i) == 0 ? (v).x : (i) == 1 ? (v).y : (i) == 2 ? (v).z : (v).w)

// ================= graph conv (+tanh, +bn1) =================
// Block = 64 atoms, 256 threads. Combined input tile [self | neighbor-sum]
// staged in SMEM; each thread computes 4 atoms x 4 output features.
template <int F, int D>
__global__ __launch_bounds__(256) void gc_kernel(
    const float* __restrict__ feat,
    const int* __restrict__ adj,
    const float* __restrict__ Ws,   // [F][64] slice for this degree
    const float* __restrict__ Wn,   // [F][64] slice (unused if D==0)
    const float* __restrict__ bias, // [64]
    const float* __restrict__ bn_g, const float* __restrict__ bn_b,
    const float* __restrict__ bn_m, const float* __restrict__ bn_v,
    float* __restrict__ out,
    int atom0, int cnt)
{
    constexpr int SUMO = (F == 75) ? 76 : 64;       // offset of neighbor-sum half
    constexpr int PAD  = (F == 75) ? 156 : 132;     // row stride (bank-safe, f4-aligned)
    constexpr int K4   = (F == 75) ? 72 : 64;       // float4-chunked span of F

    __shared__ float s_x[64][PAD];
    __shared__ int   s_adj[64][D > 0 ? D : 1];

    const int t    = threadIdx.x;
    const int ablk = blockIdx.x * 64;
    const int nat  = min(64, cnt - ablk);

    if (D > 0) {
        for (int idx = t; idx < nat * D; idx += 256) {
            int a = idx / D, m = idx - a * D;
            s_adj[a][m] = adj[(ablk + a) * D + m];
        }
        __syncthreads();
    }

    // ---- stage self + neighbor-sum ----
    if (F == 75) {
        for (int idx = t; idx < nat * 75; idx += 256) {
            int a = idx / 75, k = idx - a * 75;
            int gi = atom0 + ablk + a;
            s_x[a][k] = feat[gi * 75 + k];
            if (D > 0) {
                float s = 0.f;
                #pragma unroll
                for (int m = 0; m < D; m++)
                    s += feat[s_adj[a][m] * 75 + k];
                s_x[a][SUMO + k] = s;
            }
        }
    } else {  // F == 64, float4 path
        for (int idx = t; idx < nat * 16; idx += 256) {
            int a = idx >> 4, q = idx & 15;
            int gi = atom0 + ablk + a;
            float4* row = (float4*)s_x[a];
            row[q] = *(const float4*)(feat + (size_t)gi * 64 + q * 4);
            if (D > 0) {
                float4 s = make_float4(0.f, 0.f, 0.f, 0.f);
                #pragma unroll
                for (int m = 0; m < D; m++) {
                    float4 u = *(const float4*)(feat + (size_t)s_adj[a][m] * 64 + q * 4);
                    s.x += u.x; s.y += u.y; s.z += u.z; s.w += u.w;
                }
                row[16 + q] = s;
            }
        }
    }
    __syncthreads();

    // ---- compute: 4 atoms x 4 features per thread ----
    const int j   = (t & 15) * 4;   // output feature quad
    const int grp = t >> 4;         // 16 groups x 4 atoms

    float acc[4][4];
    {
        float4 b4 = *(const float4*)(bias + j);
        #pragma unroll
        for (int r = 0; r < 4; r++) {
            acc[r][0] = b4.x; acc[r][1] = b4.y; acc[r][2] = b4.z; acc[r][3] = b4.w;
        }
    }

    // Ws part (self), then Wn part (neighbor sum)
    #pragma unroll 1
    for (int part = 0; part < (D > 0 ? 2 : 1); part++) {
        const float* __restrict__ W = part ? Wn : Ws;
        const int xoff = part ? SUMO : 0;
        for (int k0 = 0; k0 < K4; k0 += 4) {
            float4 w[4];
            #pragma unroll
            for (int kk = 0; kk < 4; kk++)
                w[kk] = *(const float4*)(W + (k0 + kk) * 64 + j);
            #pragma unroll
            for (int r = 0; r < 4; r++) {
                float4 xv = *(const float4*)&s_x[grp * 4 + r][xoff + k0];
                #pragma unroll
                for (int kk = 0; kk < 4; kk++) {
                    float x = COMP(xv, kk);
                    acc[r][0] = fmaf(x, w[kk].x, acc[r][0]);
                    acc[r][1] = fmaf(x, w[kk].y, acc[r][1]);
                    acc[r][2] = fmaf(x, w[kk].z, acc[r][2]);
                    acc[r][3] = fmaf(x, w[kk].w, acc[r][3]);
                }
            }
        }
        if (F == 75) {  // tail k = 72..74
            #pragma unroll
            for (int k = 72; k < 75; k++) {
                float4 w = *(const float4*)(W + k * 64 + j);
                #pragma unroll
                for (int r = 0; r < 4; r++) {
                    float x = s_x[grp * 4 + r][xoff + k];
                    acc[r][0] = fmaf(x, w.x, acc[r][0]);
                    acc[r][1] = fmaf(x, w.y, acc[r][1]);
                    acc[r][2] = fmaf(x, w.z, acc[r][2]);
                    acc[r][3] = fmaf(x, w.w, acc[r][3]);
                }
            }
        }
    }

    // ---- bn(tanh(acc)) and store ----
    float4 g4 = *(const float4*)(bn_g + j);
    float4 v4 = *(const float4*)(bn_v + j);
    float4 b4 = *(const float4*)(bn_b + j);
    float4 m4 = *(const float4*)(bn_m + j);
    float sc[4], sh[4];
    #pragma unroll
    for (int c = 0; c < 4; c++) {
        sc[c] = COMP(g4, c) * rsqrtf(COMP(v4, c) + 1e-3f);
        sh[c] = COMP(b4, c) - COMP(m4, c) * sc[c];
    }

    #pragma unroll
    for (int r = 0; r < 4; r++) {
        int a = grp * 4 + r;
        if (a < nat) {
            int gi = atom0 + ablk + a;
            float4 o;
            o.x = sc[0] * tanh_fast(acc[r][0]) + sh[0];
            o.y = sc[1] * tanh_fast(acc[r][1]) + sh[1];
            o.z = sc[2] * tanh_fast(acc[r][2]) + sh[2];
            o.w = sc[3] * tanh_fast(acc[r][3]) + sh[3];
            *(float4*)(out + (size_t)gi * 64 + j) = o;
        }
    }
}

// ================= graph pool (float4) =================
__global__ __launch_bounds__(256) void pool_kernel(
    const float4* __restrict__ in, float4* __restrict__ out,
    const int* __restrict__ a1, const int* __restrict__ a2,
    const int* __restrict__ a3, const int* __restrict__ a4,
    const int* __restrict__ a5, const int* __restrict__ a6)
{
    int idx  = blockIdx.x * 256 + threadIdx.x;  // NA*16 total
    int atom = idx >> 4;
    int q    = idx & 15;
    float4 v = in[idx];

    if (atom >= 20000) {
        const int* ap; int d, li;
        if      (atom < 100000) { d = 1; ap = a1; li = atom - 20000;  }
        else if (atom < 250000) { d = 2; ap = a2; li = atom - 100000; }
        else if (atom < 400000) { d = 3; ap = a3; li = atom - 250000; }
        else if (atom < 475000) { d = 4; ap = a4; li = atom - 400000; }
        else if (atom < 495000) { d = 5; ap = a5; li = atom - 475000; }
        else                    { d = 6; ap = a6; li = atom - 495000; }
        for (int m = 0; m < d; m++) {
            int nb = ap[li * d + m];
            float4 u = in[nb * 16 + q];
            v.x = fmaxf(v.x, u.x); v.y = fmaxf(v.y, u.y);
            v.z = fmaxf(v.z, u.z); v.w = fmaxf(v.w, u.w);
        }
    }
    out[idx] = v;
}

// ================= dense1 [64]->[128] + tanh + bn3, fused segment gather =================
// Block = 64 atoms, 256 threads; each thread: 8 atoms x 4 features.
__global__ __launch_bounds__(256) void dense1_gather_kernel(
    const float* __restrict__ in,
    const int* __restrict__ membership,
    const float* __restrict__ W,   // [64][128]
    const float* __restrict__ b,   // [128]
    const float* __restrict__ bn_g, const float* __restrict__ bn_b,
    const float* __restrict__ bn_m, const float* __restrict__ bn_v,
    float* __restrict__ gsum, unsigned* __restrict__ gmax,
    int cnt)
{
    __shared__ float s_in[64][68];
    __shared__ int   s_mem[64];

    const int t    = threadIdx.x;
    const int ablk = blockIdx.x * 64;
    const int nat  = min(64, cnt - ablk);

    for (int idx = t; idx < nat * 16; idx += 256) {
        int a = idx >> 4, q = idx & 15;
        *(float4*)&s_in[a][q * 4] = *(const float4*)(in + (size_t)(ablk + a) * 64 + q * 4);
    }
    if (t < nat) s_mem[t] = membership[ablk + t];
    __syncthreads();

    const int j   = (t & 31) * 4;   // 128 outputs
    const int grp = t >> 5;         // 8 groups x 8 atoms (grp warp-uniform -> LDS broadcast)

    float acc[8][4];
    {
        float4 b4 = *(const float4*)(b + j);
        #pragma unroll
        for (int r = 0; r < 8; r++) {
            acc[r][0] = b4.x; acc[r][1] = b4.y; acc[r][2] = b4.z; acc[r][3] = b4.w;
        }
    }

    for (int k0 = 0; k0 < 64; k0 += 4) {
        float4 w[4];
        #pragma unroll
        for (int kk = 0; kk < 4; kk++)
            w[kk] = *(const float4*)(W + (k0 + kk) * 128 + j);
        #pragma unroll
        for (int r = 0; r < 8; r++) {
            float4 xv = *(const float4*)&s_in[grp * 8 + r][k0];
            #pragma unroll
            for (int kk = 0; kk < 4; kk++) {
                float x = COMP(xv, kk);
                acc[r][0] = fmaf(x, w[kk].x, acc[r][0]);
                acc[r][1] = fmaf(x, w[kk].y, acc[r][1]);
                acc[r][2] = fmaf(x, w[kk].z, acc[r][2]);
                acc[r][3] = fmaf(x, w[kk].w, acc[r][3]);
            }
        }
    }

    float4 g4 = *(const float4*)(bn_g + j);
    float4 v4 = *(const float4*)(bn_v + j);
    float4 bb4 = *(const float4*)(bn_b + j);
    float4 m4 = *(const float4*)(bn_m + j);
    float sc[4], sh[4];
    #pragma unroll
    for (int c = 0; c < 4; c++) {
        sc[c] = COMP(g4, c) * rsqrtf(COMP(v4, c) + 1e-3f);
        sh[c] = COMP(bb4, c) - COMP(m4, c) * sc[c];
    }

    #pragma unroll
    for (int r = 0; r < 8; r++) {
        int a = grp * 8 + r;
        if (a < nat) {
            int m = s_mem[a];
            #pragma unroll
            for (int c = 0; c < 4; c++) {
                float v = sc[c] * tanh_fast(acc[r][c]) + sh[c];
                atomicAdd(&gsum[m * 128 + j + c], v);
                atomicMax(&gmax[m * 128 + j + c], enc_f(v));
            }
        }
    }
}

// ================= gather init =================
__global__ void init_gather_kernel(float* __restrict__ gsum, unsigned* __restrict__ gmax)
{
    int idx = blockIdx.x * 256 + threadIdx.x;
    if (idx < 1024 * 128) { gsum[idx] = 0.f; gmax[idx] = 0u; }
}

// ================= head: tanh(concat) -> sigmoid(dense 256->64) -> dense 64->1 =================
__global__ void head_kernel(const float* __restrict__ gsum, const unsigned* __restrict__ gmax,
                            const float* __restrict__ d2W, const float* __restrict__ d2b,
                            const float* __restrict__ d3W, const float* __restrict__ d3b,
                            float* __restrict__ out)
{
    __shared__ float sg[256];
    __shared__ float sred[64];
    const int row = blockIdx.x;
    const int t   = threadIdx.x;  // 64 threads

    for (int k = t; k < 256; k += 64) {
        float v = (k < 128) ? gsum[row * 128 + k] : dec_f(gmax[row * 128 + (k - 128)]);
        sg[k] = tanh_fast(v);
    }
    __syncthreads();

    float acc = d2b[t];
    for (int k = 0; k < 256; k++)
        acc = fmaf(sg[k], d2W[k * 64 + t], acc);
    float s = 1.f / (1.f + expf(-acc));

    sred[t] = s * d3W[t];
    __syncthreads();
    if (t < 32) {
        float x = sred[t] + sred[t + 32];
        #pragma unroll
        for (int off = 16; off; off >>= 1)
            x += __shfl_down_sync(0xffffffffu, x, off);
        if (t == 0) out[row] = x + d3b[0];
    }
}

// ================= dispatch helpers =================
template <int F>
static void launch_gc(int d, const float* feat, const int* adj,
                      const float* Ws, const float* Wn, const float* bias,
                      const float* bg, const float* bb, const float* bm, const float* bv,
                      float* out, int atom0, int cnt)
{
    dim3 grid((cnt + 63) / 64);
    switch (d) {
    case 0: gc_kernel<F,0><<<grid,256>>>(feat,adj,Ws,Wn,bias,bg,bb,bm,bv,out,atom0,cnt); break;
    case 1: gc_kernel<F,1><<<grid,256>>>(feat,adj,Ws,Wn,bias,bg,bb,bm,bv,out,atom0,cnt); break;
    case 2: gc_kernel<F,2><<<grid,256>>>(feat,adj,Ws,Wn,bias,bg,bb,bm,bv,out,atom0,cnt); break;
    case 3: gc_kernel<F,3><<<grid,256>>>(feat,adj,Ws,Wn,bias,bg,bb,bm,bv,out,atom0,cnt); break;
    case 4: gc_kernel<F,4><<<grid,256>>>(feat,adj,Ws,Wn,bias,bg,bb,bm,bv,out,atom0,cnt); break;
    case 5: gc_kernel<F,5><<<grid,256>>>(feat,adj,Ws,Wn,bias,bg,bb,bm,bv,out,atom0,cnt); break;
    case 6: gc_kernel<F,6><<<grid,256>>>(feat,adj,Ws,Wn,bias,bg,bb,bm,bv,out,atom0,cnt); break;
    }
}

// ================= launch =================
extern "C" void kernel_launch(void* const* d_in, const int* in_sizes, int n_in,
                              void* d_out, int out_size)
{
    const float* feat       = (const float*)d_in[0];
    const int*   membership = (const int*)d_in[1];
    const int*   adj[6]     = {(const int*)d_in[2], (const int*)d_in[3], (const int*)d_in[4],
                               (const int*)d_in[5], (const int*)d_in[6], (const int*)d_in[7]};
    const float* gc1_Wn = (const float*)d_in[8];
    const float* gc1_Ws = (const float*)d_in[9];
    const float* gc1_b  = (const float*)d_in[10];
    const float* gc2_Wn = (const float*)d_in[11];
    const float* gc2_Ws = (const float*)d_in[12];
    const float* gc2_b  = (const float*)d_in[13];
    const float* bn1g = (const float*)d_in[14];
    const float* bn1b = (const float*)d_in[15];
    const float* bn1m = (const float*)d_in[16];
    const float* bn1v = (const float*)d_in[17];
    const float* bn3g = (const float*)d_in[18];
    const float* bn3b = (const float*)d_in[19];
    const float* bn3m = (const float*)d_in[20];
    const float* bn3v = (const float*)d_in[21];
    const float* d1W = (const float*)d_in[22];
    const float* d1b = (const float*)d_in[23];
    const float* d2W = (const float*)d_in[24];
    const float* d2b = (const float*)d_in[25];
    const float* d3W = (const float*)d_in[26];
    const float* d3b = (const float*)d_in[27];

    float *h1, *h2, *gsum; unsigned* gmax;
    cudaGetSymbolAddress((void**)&h1, g_h1);
    cudaGetSymbolAddress((void**)&h2, g_h2);
    cudaGetSymbolAddress((void**)&gsum, g_gsum);
    cudaGetSymbolAddress((void**)&gmax, g_gmax);

    // ---- gc1 (+tanh +bn1): feat[NA,75] -> h1[NA,64]
    for (int d = 0; d <= 6; d++) {
        launch_gc<75>(d, feat, d ? adj[d - 1] : nullptr,
                      gc1_Ws + d * 75 * 64, d ? gc1_Wn + (d - 1) * 75 * 64 : nullptr,
                      gc1_b + d * 64, bn1g, bn1b, bn1m, bn1v,
                      h1, H_DEG_OFF[d], H_DEG_CNT[d]);
    }

    // ---- pool1: h1 -> h2
    pool_kernel<<<NA * 16 / 256, 256>>>((const float4*)h1, (float4*)h2,
                                        adj[0], adj[1], adj[2], adj[3], adj[4], adj[5]);

    // ---- gc2 (+tanh +bn1): h2[NA,64] -> h1[NA,64]
    for (int d = 0; d <= 6; d++) {
        launch_gc<64>(d, h2, d ? adj[d - 1] : nullptr,
                      gc2_Ws + d * 64 * 64, d ? gc2_Wn + (d - 1) * 64 * 64 : nullptr,
                      gc2_b + d * 64, bn1g, bn1b, bn1m, bn1v,
                      h1, H_DEG_OFF[d], H_DEG_CNT[d]);
    }

    // ---- pool2: h1 -> h2
    pool_kernel<<<NA * 16 / 256, 256>>>((const float4*)h1, (float4*)h2,
                                        adj[0], adj[1], adj[2], adj[3], adj[4], adj[5]);

    // ---- init gather accumulators, then fused dense1 + segment gather
    init_gather_kernel<<<(1024 * 128 + 255) / 256, 256>>>(gsum, gmax);
    dense1_gather_kernel<<<(NA + 63) / 64, 256>>>(h2, membership, d1W, d1b,
                                                  bn3g, bn3b, bn3m, bn3v,
                                                  gsum, gmax, NA);

    // ---- head
    head_kernel<<<1024, 64>>>(gsum, gmax, d2W, d2b, d3W, d3b, (float*)d_out);
}